// round 12
// baseline (speedup 1.0000x reference)
#include <cuda_runtime.h>
#include <math.h>

// ---------------------------------------------------------------------------
// GLSDE R8: R5 output-tiled encoder + register diet for 3 blocks/SM.
//  - Wih weights moved to SMEM (transient per-step loads, q==0 threads)
//  - bt-loop split into two 2-bt passes (8 live acc chains instead of 16)
//  - __launch_bounds__(192,3): 18 warps/SM, grid 512 -> 1.15 waves
// Output: [x_recon (B*T) | mu (B*16) | log_var (B*16)] float32
// ---------------------------------------------------------------------------

#define BSZ 2048
#define TLEN 512
#define IND 6
#define HID 64
#define LAT 16
#define BT 4
#define NTHR 192
#define NRG 48       // row groups (192 gate rows / 4 rows-per-thread)
#define RPT 4        // gate rows per thread
#define KQ 16        // k-slice width per quarter

typedef unsigned long long u64;

__device__ float g_hT[BSZ * HID];
__device__ float g_xg[BSZ * 3];

__device__ __forceinline__ u64 pack2(float lo, float hi) {
    u64 r; asm("mov.b64 %0, {%1,%2};" : "=l"(r) : "f"(lo), "f"(hi)); return r;
}
__device__ __forceinline__ void unpack2(u64 v, float& lo, float& hi) {
    asm("mov.b64 {%0,%1}, %2;" : "=f"(lo), "=f"(hi) : "l"(v));
}
__device__ __forceinline__ void ffma2(u64& d, u64 a, u64 b) {
    asm("fma.rn.f32x2 %0, %1, %2, %0;" : "+l"(d) : "l"(a), "l"(b));
}
__device__ __forceinline__ float sig_fast(float v) {
    return __fdividef(1.0f, 1.0f + __expf(-v));
}
__device__ __forceinline__ float tanh_fast(float x) {
    float t = __expf(-2.0f * fabsf(x));
    return copysignf(__fdividef(1.0f - t, 1.0f + t), x);
}

// ---------------------------------------------------------------------------
// Kernel A: encoder GRU scan, output-tiled (R5 mapping).
// tid -> (rg = tid % 48, q = tid / 48). Thread computes gate rows
// 4rg..4rg+3 over k in [16q, 16q+16) for BT batch rows.
// ---------------------------------------------------------------------------
__global__ void __launch_bounds__(NTHR, 3) enc_kernel(
    const float* __restrict__ x,
    const float* __restrict__ Wih, const float* __restrict__ Whh,
    const float* __restrict__ bih, const float* __restrict__ bhh)
{
    const int tid = threadIdx.x;
    const int rg  = tid % NRG;
    const int q   = tid / NRG;        // k-quarter 0..3
    const int r0  = rg * RPT;         // first gate row of this thread
    const int b0  = blockIdx.x * BT;

    __shared__ __align__(16) float h_sh[BT][HID];
    __shared__ __align__(16) float x_sh[2][BT][8];       // 6 used, pad to 8
    __shared__ __align__(16) float p_part[4][BT][3 * HID];
    __shared__ __align__(16) float p_xn[BT][HID];
    __shared__ __align__(16) float sWih[3 * HID][8];     // 6 used, pad to 8

    // Whh slice: 4 rows x 16 k, packed f32x2 along k (persistent registers)
    u64 w2[RPT][KQ / 2];
#pragma unroll
    for (int r = 0; r < RPT; r++) {
        const u64* wp = (const u64*)(Whh + (size_t)(r0 + r) * HID + q * KQ);
#pragma unroll
        for (int k = 0; k < KQ / 2; k++) w2[r][k] = wp[k];
    }

    // Wih rows -> SMEM (saves ~24 persistent regs vs R5)
    for (int i = tid; i < 3 * HID * IND; i += NTHR) {
        int row = i / IND, d = i % IND;
        sWih[row][d] = Wih[i];
    }

    // biases (small: 8 regs), only meaningful on q==0 threads
    const bool isn = (r0 >= 2 * HID);          // rows 128..191 = n-gate
    float bsum[RPT], bxn[RPT];
    if (q == 0) {
#pragma unroll
        for (int r = 0; r < RPT; r++) {
            bsum[r] = bhh[r0 + r] + (isn ? 0.0f : bih[r0 + r]);
            bxn[r]  = isn ? bih[r0 + r] : 0.0f;
        }
    }

    for (int i = tid; i < BT * HID; i += NTHR) ((float*)h_sh)[i] = 0.0f;
    if (tid < BT * IND) {
        int bt = tid / IND, d = tid % IND;
        x_sh[0][bt][d] = x[(size_t)(b0 + bt) * (TLEN * IND) + d];
    }
    __syncthreads();

    for (int t = 0; t < TLEN; t++) {
        const int cur = t & 1, nxt = cur ^ 1;
        if (t + 1 < TLEN && tid < BT * IND) {
            int bt = tid / IND, d = tid % IND;
            x_sh[nxt][bt][d] = x[(size_t)(b0 + bt) * (TLEN * IND) + (t + 1) * IND + d];
        }

        // ---- dot phase: two passes of 2 bt (8 live packed chains each) ----
        float s[RPT][BT];
#pragma unroll
        for (int bp = 0; bp < 2; bp++) {
            u64 acc[RPT][2];
#pragma unroll
            for (int r = 0; r < RPT; r++) { acc[r][0] = 0ULL; acc[r][1] = 0ULL; }
#pragma unroll
            for (int k16 = 0; k16 < KQ / 4; k16++) {
#pragma unroll
                for (int b2 = 0; b2 < 2; b2++) {
                    const int bt = bp * 2 + b2;
                    ulonglong2 hv =
                        ((const ulonglong2*)(&h_sh[bt][q * KQ]))[k16];
#pragma unroll
                    for (int r = 0; r < RPT; r++) {
                        ffma2(acc[r][b2], w2[r][2 * k16 + 0], hv.x);
                        ffma2(acc[r][b2], w2[r][2 * k16 + 1], hv.y);
                    }
                }
            }
#pragma unroll
            for (int r = 0; r < RPT; r++)
#pragma unroll
                for (int b2 = 0; b2 < 2; b2++) {
                    float lo, hi; unpack2(acc[r][b2], lo, hi);
                    s[r][bp * 2 + b2] = lo + hi;
                }
        }

        // ---- x-gates + biases (q==0 threads), Wih read from SMEM ----
        if (q == 0) {
#pragma unroll
            for (int r = 0; r < RPT; r++) {
                const u64* wxp = (const u64*)sWih[r0 + r];
                const u64 wa = wxp[0], wb = wxp[1], wc = wxp[2];
#pragma unroll
                for (int bt = 0; bt < BT; bt++) {
                    const u64* xp = (const u64*)x_sh[cur][bt];
                    u64 xa = 0ULL;
                    ffma2(xa, wa, xp[0]);
                    ffma2(xa, wb, xp[1]);
                    ffma2(xa, wc, xp[2]);
                    float xl, xh; unpack2(xa, xl, xh);
                    float xg = xl + xh;
                    if (!isn) {
                        s[r][bt] += bsum[r] + xg;
                    } else {
                        s[r][bt] += bsum[r];
                        p_xn[bt][r0 + r - 2 * HID] = bxn[r] + xg;
                    }
                }
            }
        }

        // coalesced float4 partial stores (rows are consecutive)
#pragma unroll
        for (int bt = 0; bt < BT; bt++) {
            float4 v = make_float4(s[0][bt], s[1][bt], s[2][bt], s[3][bt]);
            *(float4*)&p_part[q][bt][r0] = v;
        }
        __syncthreads();

        // ---- nonlin phase: 128 threads, 2 h-elements each (float2) ----
        if (tid < BT * HID / 2) {
            const int bt = tid >> 5;
            const int j0 = (tid & 31) * 2;
            float2 pr = *(const float2*)&p_part[0][bt][j0];
            float2 pz = *(const float2*)&p_part[0][bt][HID + j0];
            float2 pn = *(const float2*)&p_part[0][bt][2 * HID + j0];
#pragma unroll
            for (int qq = 1; qq < 4; qq++) {
                float2 a = *(const float2*)&p_part[qq][bt][j0];
                float2 b = *(const float2*)&p_part[qq][bt][HID + j0];
                float2 c = *(const float2*)&p_part[qq][bt][2 * HID + j0];
                pr.x += a.x; pr.y += a.y;
                pz.x += b.x; pz.y += b.y;
                pn.x += c.x; pn.y += c.y;
            }
            float2 xn2 = *(const float2*)&p_xn[bt][j0];
            float2 hov = *(const float2*)&h_sh[bt][j0];
            float r0v = sig_fast(pr.x), r1v = sig_fast(pr.y);
            float z0v = sig_fast(pz.x), z1v = sig_fast(pz.y);
            float n0v = tanh_fast(fmaf(r0v, pn.x, xn2.x));
            float n1v = tanh_fast(fmaf(r1v, pn.y, xn2.y));
            float2 hnew;
            hnew.x = (1.0f - z0v) * n0v + z0v * hov.x;
            hnew.y = (1.0f - z1v) * n1v + z1v * hov.y;
            *(float2*)&h_sh[bt][j0] = hnew;
        }
        __syncthreads();
    }

    if (tid < BT * HID / 2) {
        const int bt = tid >> 5;
        const int j0 = (tid & 31) * 2;
        float2 hv = *(const float2*)&h_sh[bt][j0];
        *(float2*)&g_hT[(size_t)(b0 + bt) * HID + j0] = hv;
    }
}

// ---------------------------------------------------------------------------
// Kernel B: per-batch: mu/lv heads, z0, RK4(64), decoder fc + x-gates.
// ---------------------------------------------------------------------------
__global__ void __launch_bounds__(32) mid_kernel(
    const float* __restrict__ fc_mu_W, const float* __restrict__ fc_mu_b,
    const float* __restrict__ fc_lv_W, const float* __restrict__ fc_lv_b,
    const float* __restrict__ ode_W,   const float* __restrict__ ode_b,
    const float* __restrict__ dec_fc_W, const float* __restrict__ dec_fc_b,
    const float* __restrict__ dec_Wih, const float* __restrict__ dec_bih,
    float* __restrict__ out_mu, float* __restrict__ out_lv)
{
    __shared__ __align__(16) float sMu[LAT * HID], sLv[LAT * HID], sDW[HID * LAT];
    __shared__ __align__(16) float sOW[LAT * LAT], sWih[3 * HID];
    __shared__ float sOb[LAT], sMub[LAT], sLvb[LAT], sDb[HID], sBih[3];

    const int tid = threadIdx.x;
    for (int i = tid; i < LAT * HID; i += 32) {
        sMu[i] = fc_mu_W[i]; sLv[i] = fc_lv_W[i]; sDW[i] = dec_fc_W[i];
    }
    for (int i = tid; i < LAT * LAT; i += 32) sOW[i] = ode_W[i];
    for (int i = tid; i < 3 * HID;  i += 32) sWih[i] = dec_Wih[i];
    if (tid < LAT) { sOb[tid] = ode_b[tid]; sMub[tid] = fc_mu_b[tid]; sLvb[tid] = fc_lv_b[tid]; }
    if (tid < 3)   sBih[tid] = dec_bih[tid];
    for (int i = tid; i < HID; i += 32) sDb[i] = dec_fc_b[i];
    __syncthreads();

    const int b = blockIdx.x * 32 + tid;
    if (b >= BSZ) return;

    u64 hv2[HID / 2];
    const u64* hvp = (const u64*)(g_hT + (size_t)b * HID);
#pragma unroll
    for (int k = 0; k < HID / 2; k++) hv2[k] = hvp[k];

    const u64* sMu2 = (const u64*)sMu;
    const u64* sLv2 = (const u64*)sLv;
    const u64* sOW2 = (const u64*)sOW;
    const u64* sDW2 = (const u64*)sDW;

    float z[LAT];
#pragma unroll
    for (int i = 0; i < LAT; i++) {
        u64 am = 0ULL, al = 0ULL;
#pragma unroll
        for (int k = 0; k < HID / 2; k++) {
            ffma2(am, sMu2[i * (HID / 2) + k], hv2[k]);
            ffma2(al, sLv2[i * (HID / 2) + k], hv2[k]);
        }
        float m0, m1, l0, l1;
        unpack2(am, m0, m1); unpack2(al, l0, l1);
        float m = sMub[i] + m0 + m1;
        float l = sLvb[i] + l0 + l1;
        out_mu[(size_t)b * LAT + i] = m;
        out_lv[(size_t)b * LAT + i] = l;
        z[i] = m + expf(0.5f * l);
    }

    const float hs = 1.0f / 64.0f;
    float k1[LAT], k2[LAT], k3[LAT], k4[LAT], zt[LAT];

#define ODE_EVAL(SRC, DST)                                                    \
    {                                                                         \
        u64 zp[LAT / 2];                                                      \
        _Pragma("unroll")                                                     \
        for (int m = 0; m < LAT / 2; m++)                                     \
            zp[m] = pack2(SRC[2 * m], SRC[2 * m + 1]);                        \
        _Pragma("unroll")                                                     \
        for (int i = 0; i < LAT; i++) {                                       \
            u64 a = 0ULL;                                                     \
            _Pragma("unroll")                                                 \
            for (int j = 0; j < LAT / 2; j++)                                 \
                ffma2(a, sOW2[i * (LAT / 2) + j], zp[j]);                     \
            float lo, hi; unpack2(a, lo, hi);                                 \
            DST[i] = fmaxf(sOb[i] + lo + hi, 0.0f);                           \
        }                                                                     \
    }

    for (int s = 0; s < 64; s++) {
        ODE_EVAL(z, k1);
#pragma unroll
        for (int i = 0; i < LAT; i++) zt[i] = fmaf(0.5f * hs, k1[i], z[i]);
        ODE_EVAL(zt, k2);
#pragma unroll
        for (int i = 0; i < LAT; i++) zt[i] = fmaf(0.5f * hs, k2[i], z[i]);
        ODE_EVAL(zt, k3);
#pragma unroll
        for (int i = 0; i < LAT; i++) zt[i] = fmaf(hs, k3[i], z[i]);
        ODE_EVAL(zt, k4);
#pragma unroll
        for (int i = 0; i < LAT; i++)
            z[i] += (hs / 6.0f) * (k1[i] + 2.0f * k2[i] + 2.0f * k3[i] + k4[i]);
    }

    u64 zp[LAT / 2];
#pragma unroll
    for (int m = 0; m < LAT / 2; m++) zp[m] = pack2(z[2 * m], z[2 * m + 1]);

    float xg0 = sBih[0], xg1 = sBih[1], xg2 = sBih[2];
#pragma unroll
    for (int j = 0; j < HID; j++) {
        u64 a = 0ULL;
#pragma unroll
        for (int i = 0; i < LAT / 2; i++) ffma2(a, sDW2[j * (LAT / 2) + i], zp[i]);
        float lo, hi; unpack2(a, lo, hi);
        float av = fmaxf(sDb[j] + lo + hi, 0.0f);
        xg0 = fmaf(sWih[0 * HID + j], av, xg0);
        xg1 = fmaf(sWih[1 * HID + j], av, xg1);
        xg2 = fmaf(sWih[2 * HID + j], av, xg2);
    }
    g_xg[(size_t)b * 3 + 0] = xg0;
    g_xg[(size_t)b * 3 + 1] = xg1;
    g_xg[(size_t)b * 3 + 2] = xg2;
}

// ---------------------------------------------------------------------------
// Kernel C: decoder GRU, hidden size 1, constant input gates. Thread per batch.
// ---------------------------------------------------------------------------
__global__ void __launch_bounds__(64) dec_kernel(
    const float* __restrict__ dec_Whh, const float* __restrict__ dec_bhh,
    float* __restrict__ out)
{
    const int b = blockIdx.x * 64 + threadIdx.x;
    if (b >= BSZ) return;

    const float xr = g_xg[(size_t)b * 3 + 0];
    const float xz = g_xg[(size_t)b * 3 + 1];
    const float xn = g_xg[(size_t)b * 3 + 2];
    const float w0 = dec_Whh[0], w1 = dec_Whh[1], w2 = dec_Whh[2];
    const float c0 = dec_bhh[0], c1 = dec_bhh[1], c2 = dec_bhh[2];

    float h = 0.0f;
    float4* outp = (float4*)(out + (size_t)b * TLEN);
    for (int t = 0; t < TLEN; t += 4) {
        float4 buf;
        float* bf = (float*)&buf;
#pragma unroll
        for (int qq = 0; qq < 4; qq++) {
            float r  = sig_fast(xr + fmaf(w0, h, c0));
            float zg = sig_fast(xz + fmaf(w1, h, c1));
            float n  = tanh_fast(xn + r * fmaf(w2, h, c2));
            h = (1.0f - zg) * n + zg * h;
            bf[qq] = h;
        }
        outp[t >> 2] = buf;
    }
}

// ---------------------------------------------------------------------------
extern "C" void kernel_launch(void* const* d_in, const int* in_sizes, int n_in,
                              void* d_out, int out_size)
{
    const float* x        = (const float*)d_in[0];
    const float* enc_Wih  = (const float*)d_in[1];
    const float* enc_Whh  = (const float*)d_in[2];
    const float* enc_bih  = (const float*)d_in[3];
    const float* enc_bhh  = (const float*)d_in[4];
    const float* fc_mu_W  = (const float*)d_in[5];
    const float* fc_mu_b  = (const float*)d_in[6];
    const float* fc_lv_W  = (const float*)d_in[7];
    const float* fc_lv_b  = (const float*)d_in[8];
    const float* ode_W    = (const float*)d_in[9];
    const float* ode_b    = (const float*)d_in[10];
    const float* dec_fc_W = (const float*)d_in[11];
    const float* dec_fc_b = (const float*)d_in[12];
    const float* dec_Wih  = (const float*)d_in[13];
    const float* dec_Whh  = (const float*)d_in[14];
    const float* dec_bih  = (const float*)d_in[15];
    const float* dec_bhh  = (const float*)d_in[16];

    float* out = (float*)d_out;
    float* out_xrec = out;                       // B*T
    float* out_mu   = out + (size_t)BSZ * TLEN;  // B*16
    float* out_lv   = out_mu + (size_t)BSZ * LAT;

    enc_kernel<<<BSZ / BT, NTHR>>>(x, enc_Wih, enc_Whh, enc_bih, enc_bhh);
    mid_kernel<<<BSZ / 32, 32>>>(fc_mu_W, fc_mu_b, fc_lv_W, fc_lv_b,
                                 ode_W, ode_b, dec_fc_W, dec_fc_b,
                                 dec_Wih, dec_bih, out_mu, out_lv);
    dec_kernel<<<BSZ / 64, 64>>>(dec_Whh, dec_bhh, out_xrec);
}

// round 14
// speedup vs baseline: 2.0121x; 2.0121x over previous
#include <cuda_runtime.h>
#include <math.h>

// ---------------------------------------------------------------------------
// GLSDE R9: exact R5 encoder inner loop, BT 4 -> 8 (two 4-bt passes).
//  - grid 256 blocks @ 2/SM -> single wave (R5 ran 1.73 waves)
//  - per-step fixed overhead amortized over 2x batch rows
//  - x-gate work split across q==0 (bt 0-3) and q==1 (bt 4-7) threads
// Output: [x_recon (B*T) | mu (B*16) | log_var (B*16)] float32
// ---------------------------------------------------------------------------

#define BSZ 2048
#define TLEN 512
#define IND 6
#define HID 64
#define LAT 16
#define BT 8
#define NTHR 192
#define NRG 48       // row groups (192 gate rows / 4 rows-per-thread)
#define RPT 4        // gate rows per thread
#define KQ 16        // k-slice width per quarter

typedef unsigned long long u64;

__device__ float g_hT[BSZ * HID];
__device__ float g_xg[BSZ * 3];

__device__ __forceinline__ u64 pack2(float lo, float hi) {
    u64 r; asm("mov.b64 %0, {%1,%2};" : "=l"(r) : "f"(lo), "f"(hi)); return r;
}
__device__ __forceinline__ void unpack2(u64 v, float& lo, float& hi) {
    asm("mov.b64 {%0,%1}, %2;" : "=f"(lo), "=f"(hi) : "l"(v));
}
__device__ __forceinline__ void ffma2(u64& d, u64 a, u64 b) {
    asm("fma.rn.f32x2 %0, %1, %2, %0;" : "+l"(d) : "l"(a), "l"(b));
}
__device__ __forceinline__ float sig_fast(float v) {
    return __fdividef(1.0f, 1.0f + __expf(-v));
}
__device__ __forceinline__ float tanh_fast(float x) {
    float t = __expf(-2.0f * fabsf(x));
    return copysignf(__fdividef(1.0f - t, 1.0f + t), x);
}

// ---------------------------------------------------------------------------
// Kernel A: encoder GRU scan, output-tiled (R5 mapping), BT=8.
// tid -> (rg = tid % 48, q = tid / 48). Thread computes gate rows
// 4rg..4rg+3 over k in [16q, 16q+16) for 8 batch rows (two 4-bt passes).
// ---------------------------------------------------------------------------
__global__ void __launch_bounds__(NTHR, 2) enc_kernel(
    const float* __restrict__ x,
    const float* __restrict__ Wih, const float* __restrict__ Whh,
    const float* __restrict__ bih, const float* __restrict__ bhh)
{
    const int tid = threadIdx.x;
    const int rg  = tid % NRG;
    const int q   = tid / NRG;        // k-quarter 0..3
    const int r0  = rg * RPT;         // first gate row of this thread
    const int b0  = blockIdx.x * BT;

    __shared__ __align__(16) float h_sh[BT][HID];
    __shared__ __align__(16) float x_sh[2][BT][8];       // 6 used, pad to 8
    __shared__ __align__(16) float p_part[4][BT][3 * HID];
    __shared__ __align__(16) float p_xn[BT][HID];

    // Whh slice: 4 rows x 16 k, packed f32x2 along k (persistent registers)
    u64 w2[RPT][KQ / 2];
#pragma unroll
    for (int r = 0; r < RPT; r++) {
        const u64* wp = (const u64*)(Whh + (size_t)(r0 + r) * HID + q * KQ);
#pragma unroll
        for (int k = 0; k < KQ / 2; k++) w2[r][k] = wp[k];
    }

    // x-gate owners: q==0 handles bt 0..3, q==1 handles bt 4..7
    const bool isn = (r0 >= 2 * HID);          // rows 128..191 = n-gate
    const bool xown = (q < 2);
    const int  btx0 = q * 4;                   // first bt this thread x-gates
    u64 wx2[RPT][3];
    float bsum[RPT], bxn[RPT];
    if (xown) {
#pragma unroll
        for (int r = 0; r < RPT; r++) {
#pragma unroll
            for (int j = 0; j < 3; j++)
                wx2[r][j] = pack2(Wih[(r0 + r) * IND + 2 * j],
                                  Wih[(r0 + r) * IND + 2 * j + 1]);
            bsum[r] = bhh[r0 + r] + (isn ? 0.0f : bih[r0 + r]);
            bxn[r]  = isn ? bih[r0 + r] : 0.0f;
        }
    }

    for (int i = tid; i < BT * HID; i += NTHR) ((float*)h_sh)[i] = 0.0f;
    if (tid < BT * IND) {
        int bt = tid / IND, d = tid % IND;
        x_sh[0][bt][d] = x[(size_t)(b0 + bt) * (TLEN * IND) + d];
    }
    __syncthreads();

    for (int t = 0; t < TLEN; t++) {
        const int cur = t & 1, nxt = cur ^ 1;
        if (t + 1 < TLEN && tid < BT * IND) {
            int bt = tid / IND, d = tid % IND;
            x_sh[nxt][bt][d] = x[(size_t)(b0 + bt) * (TLEN * IND) + (t + 1) * IND + d];
        }

        // ---- dot phase: two passes, each identical to R5 (16 live chains) ----
#pragma unroll
        for (int bp = 0; bp < 2; bp++) {
            u64 acc[RPT][4];
#pragma unroll
            for (int r = 0; r < RPT; r++)
#pragma unroll
                for (int b4 = 0; b4 < 4; b4++) acc[r][b4] = 0ULL;

#pragma unroll
            for (int k16 = 0; k16 < KQ / 4; k16++) {
#pragma unroll
                for (int b4 = 0; b4 < 4; b4++) {
                    const int bt = bp * 4 + b4;
                    ulonglong2 hv =
                        ((const ulonglong2*)(&h_sh[bt][q * KQ]))[k16];
#pragma unroll
                    for (int r = 0; r < RPT; r++) {
                        ffma2(acc[r][b4], w2[r][2 * k16 + 0], hv.x);
                        ffma2(acc[r][b4], w2[r][2 * k16 + 1], hv.y);
                    }
                }
            }

            float s[RPT][4];
#pragma unroll
            for (int r = 0; r < RPT; r++)
#pragma unroll
                for (int b4 = 0; b4 < 4; b4++) {
                    float lo, hi; unpack2(acc[r][b4], lo, hi);
                    s[r][b4] = lo + hi;
                }

            // x-gates + biases for this pass's bts owned by this thread
            if (xown && btx0 == bp * 4) {
#pragma unroll
                for (int b4 = 0; b4 < 4; b4++) {
                    const int bt = bp * 4 + b4;
                    const u64* xp = (const u64*)x_sh[cur][bt];
#pragma unroll
                    for (int r = 0; r < RPT; r++) {
                        u64 xa = 0ULL;
#pragma unroll
                        for (int j = 0; j < 3; j++) ffma2(xa, wx2[r][j], xp[j]);
                        float xl, xh; unpack2(xa, xl, xh);
                        float xg = xl + xh;
                        if (!isn) {
                            s[r][b4] += bsum[r] + xg;
                        } else {
                            s[r][b4] += bsum[r];
                            p_xn[bt][r0 + r - 2 * HID] = bxn[r] + xg;
                        }
                    }
                }
            }

            // coalesced float4 partial stores (rows are consecutive)
#pragma unroll
            for (int b4 = 0; b4 < 4; b4++) {
                const int bt = bp * 4 + b4;
                float4 v = make_float4(s[0][b4], s[1][b4], s[2][b4], s[3][b4]);
                *(float4*)&p_part[q][bt][r0] = v;
            }
        }
        __syncthreads();

        // ---- nonlin phase: 256 float2 elements over 192 threads ----
        for (int idx = tid; idx < BT * HID / 2; idx += NTHR) {
            const int bt = idx >> 5;
            const int j0 = (idx & 31) * 2;
            float2 pr = *(const float2*)&p_part[0][bt][j0];
            float2 pz = *(const float2*)&p_part[0][bt][HID + j0];
            float2 pn = *(const float2*)&p_part[0][bt][2 * HID + j0];
#pragma unroll
            for (int qq = 1; qq < 4; qq++) {
                float2 a = *(const float2*)&p_part[qq][bt][j0];
                float2 b = *(const float2*)&p_part[qq][bt][HID + j0];
                float2 c = *(const float2*)&p_part[qq][bt][2 * HID + j0];
                pr.x += a.x; pr.y += a.y;
                pz.x += b.x; pz.y += b.y;
                pn.x += c.x; pn.y += c.y;
            }
            float2 xn2 = *(const float2*)&p_xn[bt][j0];
            float2 hov = *(const float2*)&h_sh[bt][j0];
            float r0v = sig_fast(pr.x), r1v = sig_fast(pr.y);
            float z0v = sig_fast(pz.x), z1v = sig_fast(pz.y);
            float n0v = tanh_fast(fmaf(r0v, pn.x, xn2.x));
            float n1v = tanh_fast(fmaf(r1v, pn.y, xn2.y));
            float2 hnew;
            hnew.x = (1.0f - z0v) * n0v + z0v * hov.x;
            hnew.y = (1.0f - z1v) * n1v + z1v * hov.y;
            *(float2*)&h_sh[bt][j0] = hnew;
        }
        __syncthreads();
    }

    for (int idx = tid; idx < BT * HID / 2; idx += NTHR) {
        const int bt = idx >> 5;
        const int j0 = (idx & 31) * 2;
        float2 hv = *(const float2*)&h_sh[bt][j0];
        *(float2*)&g_hT[(size_t)(b0 + bt) * HID + j0] = hv;
    }
}

// ---------------------------------------------------------------------------
// Kernel B: per-batch: mu/lv heads, z0, RK4(64), decoder fc + x-gates.
// ---------------------------------------------------------------------------
__global__ void __launch_bounds__(32) mid_kernel(
    const float* __restrict__ fc_mu_W, const float* __restrict__ fc_mu_b,
    const float* __restrict__ fc_lv_W, const float* __restrict__ fc_lv_b,
    const float* __restrict__ ode_W,   const float* __restrict__ ode_b,
    const float* __restrict__ dec_fc_W, const float* __restrict__ dec_fc_b,
    const float* __restrict__ dec_Wih, const float* __restrict__ dec_bih,
    float* __restrict__ out_mu, float* __restrict__ out_lv)
{
    __shared__ __align__(16) float sMu[LAT * HID], sLv[LAT * HID], sDW[HID * LAT];
    __shared__ __align__(16) float sOW[LAT * LAT], sWih[3 * HID];
    __shared__ float sOb[LAT], sMub[LAT], sLvb[LAT], sDb[HID], sBih[3];

    const int tid = threadIdx.x;
    for (int i = tid; i < LAT * HID; i += 32) {
        sMu[i] = fc_mu_W[i]; sLv[i] = fc_lv_W[i]; sDW[i] = dec_fc_W[i];
    }
    for (int i = tid; i < LAT * LAT; i += 32) sOW[i] = ode_W[i];
    for (int i = tid; i < 3 * HID;  i += 32) sWih[i] = dec_Wih[i];
    if (tid < LAT) { sOb[tid] = ode_b[tid]; sMub[tid] = fc_mu_b[tid]; sLvb[tid] = fc_lv_b[tid]; }
    if (tid < 3)   sBih[tid] = dec_bih[tid];
    for (int i = tid; i < HID; i += 32) sDb[i] = dec_fc_b[i];
    __syncthreads();

    const int b = blockIdx.x * 32 + tid;
    if (b >= BSZ) return;

    u64 hv2[HID / 2];
    const u64* hvp = (const u64*)(g_hT + (size_t)b * HID);
#pragma unroll
    for (int k = 0; k < HID / 2; k++) hv2[k] = hvp[k];

    const u64* sMu2 = (const u64*)sMu;
    const u64* sLv2 = (const u64*)sLv;
    const u64* sOW2 = (const u64*)sOW;
    const u64* sDW2 = (const u64*)sDW;

    float z[LAT];
#pragma unroll
    for (int i = 0; i < LAT; i++) {
        u64 am = 0ULL, al = 0ULL;
#pragma unroll
        for (int k = 0; k < HID / 2; k++) {
            ffma2(am, sMu2[i * (HID / 2) + k], hv2[k]);
            ffma2(al, sLv2[i * (HID / 2) + k], hv2[k]);
        }
        float m0, m1, l0, l1;
        unpack2(am, m0, m1); unpack2(al, l0, l1);
        float m = sMub[i] + m0 + m1;
        float l = sLvb[i] + l0 + l1;
        out_mu[(size_t)b * LAT + i] = m;
        out_lv[(size_t)b * LAT + i] = l;
        z[i] = m + expf(0.5f * l);
    }

    const float hs = 1.0f / 64.0f;
    float k1[LAT], k2[LAT], k3[LAT], k4[LAT], zt[LAT];

#define ODE_EVAL(SRC, DST)                                                    \
    {                                                                         \
        u64 zp[LAT / 2];                                                      \
        _Pragma("unroll")                                                     \
        for (int m = 0; m < LAT / 2; m++)                                     \
            zp[m] = pack2(SRC[2 * m], SRC[2 * m + 1]);                        \
        _Pragma("unroll")                                                     \
        for (int i = 0; i < LAT; i++) {                                       \
            u64 a = 0ULL;                                                     \
            _Pragma("unroll")                                                 \
            for (int j = 0; j < LAT / 2; j++)                                 \
                ffma2(a, sOW2[i * (LAT / 2) + j], zp[j]);                     \
            float lo, hi; unpack2(a, lo, hi);                                 \
            DST[i] = fmaxf(sOb[i] + lo + hi, 0.0f);                           \
        }                                                                     \
    }

    for (int s = 0; s < 64; s++) {
        ODE_EVAL(z, k1);
#pragma unroll
        for (int i = 0; i < LAT; i++) zt[i] = fmaf(0.5f * hs, k1[i], z[i]);
        ODE_EVAL(zt, k2);
#pragma unroll
        for (int i = 0; i < LAT; i++) zt[i] = fmaf(0.5f * hs, k2[i], z[i]);
        ODE_EVAL(zt, k3);
#pragma unroll
        for (int i = 0; i < LAT; i++) zt[i] = fmaf(hs, k3[i], z[i]);
        ODE_EVAL(zt, k4);
#pragma unroll
        for (int i = 0; i < LAT; i++)
            z[i] += (hs / 6.0f) * (k1[i] + 2.0f * k2[i] + 2.0f * k3[i] + k4[i]);
    }

    u64 zp[LAT / 2];
#pragma unroll
    for (int m = 0; m < LAT / 2; m++) zp[m] = pack2(z[2 * m], z[2 * m + 1]);

    float xg0 = sBih[0], xg1 = sBih[1], xg2 = sBih[2];
#pragma unroll
    for (int j = 0; j < HID; j++) {
        u64 a = 0ULL;
#pragma unroll
        for (int i = 0; i < LAT / 2; i++) ffma2(a, sDW2[j * (LAT / 2) + i], zp[i]);
        float lo, hi; unpack2(a, lo, hi);
        float av = fmaxf(sDb[j] + lo + hi, 0.0f);
        xg0 = fmaf(sWih[0 * HID + j], av, xg0);
        xg1 = fmaf(sWih[1 * HID + j], av, xg1);
        xg2 = fmaf(sWih[2 * HID + j], av, xg2);
    }
    g_xg[(size_t)b * 3 + 0] = xg0;
    g_xg[(size_t)b * 3 + 1] = xg1;
    g_xg[(size_t)b * 3 + 2] = xg2;
}

// ---------------------------------------------------------------------------
// Kernel C: decoder GRU, hidden size 1, constant input gates. Thread per batch.
// ---------------------------------------------------------------------------
__global__ void __launch_bounds__(64) dec_kernel(
    const float* __restrict__ dec_Whh, const float* __restrict__ dec_bhh,
    float* __restrict__ out)
{
    const int b = blockIdx.x * 64 + threadIdx.x;
    if (b >= BSZ) return;

    const float xr = g_xg[(size_t)b * 3 + 0];
    const float xz = g_xg[(size_t)b * 3 + 1];
    const float xn = g_xg[(size_t)b * 3 + 2];
    const float w0 = dec_Whh[0], w1 = dec_Whh[1], w2 = dec_Whh[2];
    const float c0 = dec_bhh[0], c1 = dec_bhh[1], c2 = dec_bhh[2];

    float h = 0.0f;
    float4* outp = (float4*)(out + (size_t)b * TLEN);
    for (int t = 0; t < TLEN; t += 4) {
        float4 buf;
        float* bf = (float*)&buf;
#pragma unroll
        for (int qq = 0; qq < 4; qq++) {
            float r  = sig_fast(xr + fmaf(w0, h, c0));
            float zg = sig_fast(xz + fmaf(w1, h, c1));
            float n  = tanh_fast(xn + r * fmaf(w2, h, c2));
            h = (1.0f - zg) * n + zg * h;
            bf[qq] = h;
        }
        outp[t >> 2] = buf;
    }
}

// ---------------------------------------------------------------------------
extern "C" void kernel_launch(void* const* d_in, const int* in_sizes, int n_in,
                              void* d_out, int out_size)
{
    const float* x        = (const float*)d_in[0];
    const float* enc_Wih  = (const float*)d_in[1];
    const float* enc_Whh  = (const float*)d_in[2];
    const float* enc_bih  = (const float*)d_in[3];
    const float* enc_bhh  = (const float*)d_in[4];
    const float* fc_mu_W  = (const float*)d_in[5];
    const float* fc_mu_b  = (const float*)d_in[6];
    const float* fc_lv_W  = (const float*)d_in[7];
    const float* fc_lv_b  = (const float*)d_in[8];
    const float* ode_W    = (const float*)d_in[9];
    const float* ode_b    = (const float*)d_in[10];
    const float* dec_fc_W = (const float*)d_in[11];
    const float* dec_fc_b = (const float*)d_in[12];
    const float* dec_Wih  = (const float*)d_in[13];
    const float* dec_Whh  = (const float*)d_in[14];
    const float* dec_bih  = (const float*)d_in[15];
    const float* dec_bhh  = (const float*)d_in[16];

    float* out = (float*)d_out;
    float* out_xrec = out;                       // B*T
    float* out_mu   = out + (size_t)BSZ * TLEN;  // B*16
    float* out_lv   = out_mu + (size_t)BSZ * LAT;

    enc_kernel<<<BSZ / BT, NTHR>>>(x, enc_Wih, enc_Whh, enc_bih, enc_bhh);
    mid_kernel<<<BSZ / 32, 32>>>(fc_mu_W, fc_mu_b, fc_lv_W, fc_lv_b,
                                 ode_W, ode_b, dec_fc_W, dec_fc_b,
                                 dec_Wih, dec_bih, out_mu, out_lv);
    dec_kernel<<<BSZ / 64, 64>>>(dec_Whh, dec_bhh, out_xrec);
}